// round 2
// baseline (speedup 1.0000x reference)
#include <cuda_runtime.h>
#include <cstdint>

// Sliding-window unfold: out[b, i, j] = x[b, i + j]
//   x:   [B, L]     = [128, 8192]  f32 (contiguous)
//   out: [B, NW, W] = [128, 8162, 31] f32,  NW = 8162, W = 31
//
// Address identity: for global output linear index l,
//   g = l / 31, j = l % 31, b = g / 8162   (PER_B = 31*8162 = 253022)
//   src = g + j + 30*b
// Over a span of 16 consecutive l values there is AT MOST ONE row start
// (W=31 > 16). Within the span src is addr0 + k, minus 30 for k >= w
// (w = 31 - j = offset of the row start). A batch-crossing row start
// (rb wraps to 0 at a new batch) needs NO -30 correction because x's
// batches are contiguous (8161+30 = 8191 = L-1, next addr is simply +1),
// so we just disable the correction when the span crosses a batch.
//
// => 2 divisions + 16 (compare,select,LDG) + 4 STG.128 per thread.

static constexpr unsigned Wc     = 31u;
static constexpr unsigned NWc    = 8162u;
static constexpr unsigned PER_B  = Wc * NWc;          // 253022
static constexpr unsigned TOTALc = 128u * PER_B;      // 32386816
static constexpr unsigned EPT    = 16u;               // elements per thread
static constexpr unsigned NTHREADS = TOTALc / EPT;    // 2024176 (exact)

__global__ __launch_bounds__(256)
void unfold16_kernel(const float* __restrict__ x, float4* __restrict__ out,
                     unsigned nthreads) {
    unsigned t = blockIdx.x * blockDim.x + threadIdx.x;
    if (t >= nthreads) return;

    unsigned l = t * EPT;
    unsigned g = l / Wc;            // global row index (const-div -> IMAD.HI)
    unsigned j = l - g * Wc;        // position within window
    unsigned b = g / NWc;           // batch (const-div -> IMAD.HI)

    const float* p = x + (g + j + 30u * b);   // src addr of element 0
    unsigned w  = Wc - j;                     // row-start offset within span
    unsigned wb = (b + 1u) * PER_B - l;       // batch-crossing offset
    if (wb < EPT) w = EPT;                    // crossing row start: addr just continues

    float v[EPT];
#pragma unroll
    for (unsigned k = 0; k < EPT; ++k) {
        const float* pk = p + k - ((k >= w) ? 30u : 0u);
        v[k] = __ldg(pk);
    }

    float4* o = out + (size_t)t * 4u;
    o[0] = make_float4(v[0],  v[1],  v[2],  v[3]);
    o[1] = make_float4(v[4],  v[5],  v[6],  v[7]);
    o[2] = make_float4(v[8],  v[9],  v[10], v[11]);
    o[3] = make_float4(v[12], v[13], v[14], v[15]);
}

extern "C" void kernel_launch(void* const* d_in, const int* in_sizes, int n_in,
                              void* d_out, int out_size) {
    const float* x = (const float*)d_in[0];
    (void)in_sizes; (void)n_in; (void)out_size;

    const int threads = 256;
    unsigned blocks = (NTHREADS + threads - 1) / threads;   // 7907
    unfold16_kernel<<<blocks, threads>>>(x, (float4*)d_out, NTHREADS);
}

// round 3
// speedup vs baseline: 1.1769x; 1.1769x over previous
#include <cuda_runtime.h>
#include <cstdint>

// Sliding-window unfold: out[b, i, j] = x[b, i + j]
//   x:   [B, L]     = [128, 8192]  f32 (contiguous)
//   out: [B, NW, W] = [128, 8162, 31] f32,  NW = 8162, W = 31
//
// Layout: thread t <-> float4 t (perfectly coalesced stores, R1-style).
// Algebra: R2's span trick at EPT=4. For output linear l = 4t:
//   g = l / 31 (global row), j = l % 31, b = g / 8162
//   src base p = x + g + j + 30*b;  within the 4-span the src addr is
//   p + k, minus 30 once a row start is crossed (k >= w, w = 31 - j).
//   A span crossing a *batch* boundary needs no correction (x batches are
//   contiguous: ...8161+30 = 8191, next addr is 8192 = start of batch b+1),
//   so the correction is disabled when the span crosses a batch.
// Cost: 2 const-divisions per 4 elements + 4 clustered LDG + 1 STG.128.

static constexpr unsigned Wc     = 31u;
static constexpr unsigned NWc    = 8162u;
static constexpr unsigned PER_B  = Wc * NWc;          // 253022
static constexpr unsigned TOTALc = 128u * PER_B;      // 32386816
static constexpr unsigned N4     = TOTALc / 4u;       // 8096704 (exact)

__global__ __launch_bounds__(256)
void unfold4_kernel(const float* __restrict__ x, float4* __restrict__ out,
                    unsigned n4) {
    unsigned t = blockIdx.x * blockDim.x + threadIdx.x;
    if (t >= n4) return;

    unsigned l = t * 4u;
    unsigned g = l / Wc;            // const-div -> IMAD.HI chain
    unsigned j = l - g * Wc;
    unsigned b = g / NWc;           // const-div -> IMAD.HI chain

    const float* p = x + (g + j + 30u * b);   // src addr of element 0
    unsigned w  = Wc - j;                     // row-start offset within span
    unsigned wb = (b + 1u) * PER_B - l;       // distance to batch boundary
    if (wb < 4u) w = 4u;                      // batch-crossing: addr continues

    float v0 = __ldg(p + 0u - ((0u >= w) ? 30u : 0u));
    float v1 = __ldg(p + 1u - ((1u >= w) ? 30u : 0u));
    float v2 = __ldg(p + 2u - ((2u >= w) ? 30u : 0u));
    float v3 = __ldg(p + 3u - ((3u >= w) ? 30u : 0u));

    out[t] = make_float4(v0, v1, v2, v3);
}

extern "C" void kernel_launch(void* const* d_in, const int* in_sizes, int n_in,
                              void* d_out, int out_size) {
    const float* x = (const float*)d_in[0];
    (void)in_sizes; (void)n_in; (void)out_size;

    const int threads = 256;
    unsigned blocks = (N4 + threads - 1) / threads;   // 31628
    unfold4_kernel<<<blocks, threads>>>(x, (float4*)d_out, N4);
}

// round 4
// speedup vs baseline: 1.5702x; 1.3342x over previous
#include <cuda_runtime.h>
#include <cstdint>

// Sliding-window unfold: out[b, i, j] = x[b, i + j]
//   x:   [B, L]     = [128, 8192]  f32
//   out: [B, NW, W] = [128, 8162, 31] f32,  NW = 8162, W = 31
//
// Key identity: src(l) = l - 30*g(l) + 30*b(l)  (g = l/31, b = g/8162)
// is CONTINUOUS: +1 per element within a row, -29 at row starts, and
// exactly +1 across batch boundaries. So a block covering 6144 output
// elements touches only <= 260 consecutive input floats -> stage in smem.
//
// Per-thread per-iteration index update (stride 256 float4 = 1024 l,
// 1024 mod 31 == 1):  j+=1; s+=34; if(j==31){j=0;s-=30;}
// plus rare batch-boundary fixup. No per-element division, no per-element
// 64-bit address math: 4 LDS + 3 SEL + 1 STG.128 per float4.

static constexpr unsigned Wc     = 31u;
static constexpr unsigned NWc    = 8162u;
static constexpr unsigned PER_B  = Wc * NWc;           // 253022
static constexpr unsigned TOTALc = 128u * PER_B;       // 32386816
static constexpr unsigned N4     = TOTALc / 4u;        // 8096704
static constexpr unsigned XN     = 128u * 8192u;       // 1048576 input elems

static constexpr int THREADS      = 256;
static constexpr int F4_PER_T     = 6;
static constexpr int F4_PER_BLOCK = THREADS * F4_PER_T;   // 1536
static constexpr unsigned L_PER_BLOCK = F4_PER_BLOCK * 4; // 6144
static constexpr int SPAN = 260;   // max src footprint: 199 + 30 + 30 + 1

__global__ __launch_bounds__(THREADS)
void unfold_smem_kernel(const float* __restrict__ x, float4* __restrict__ out) {
    __shared__ float win[SPAN];

    unsigned l0 = blockIdx.x * L_PER_BLOCK;
    unsigned g0 = l0 / Wc;                 // uniform -> UR path
    unsigned b0 = g0 / NWc;
    unsigned s0 = g0 + 30u * b0;           // window base (absolute src idx)

    // Stage the block's entire source footprint (<= 1040 B)
    for (unsigned i = threadIdx.x; i < (unsigned)SPAN; i += THREADS) {
        unsigned gi = s0 + i;
        win[i] = (gi < XN) ? __ldg(x + gi) : 0.0f;
    }
    __syncthreads();

    // Per-thread initial algebra (the only divisions this thread does)
    unsigned f = l0 / 4u + threadIdx.x;
    unsigned l = f * 4u;
    unsigned g = l / Wc;
    unsigned j = l - g * Wc;
    unsigned b = g / NWc;
    unsigned s = (g + j + 30u * b) - s0;   // relative src of element 0
    unsigned nextB = (b + 1u) * PER_B;

#pragma unroll
    for (int m = 0; m < F4_PER_T; ++m) {
        if (f < N4) {
            unsigned w = Wc - j;               // row start at k >= w (w >= 1)
            if (nextB - l < 4u) w = 4u;        // batch boundary in span: src continues
            float v0 = win[s];
            float v1 = win[s + 1u - ((1u >= w) ? 30u : 0u)];
            float v2 = win[s + 2u - ((2u >= w) ? 30u : 0u)];
            float v3 = win[s + 3u - ((3u >= w) ? 30u : 0u)];
            out[f] = make_float4(v0, v1, v2, v3);
        }
        // advance by 256 float4s = 1024 l  (1024 = 33*31 + 1)
        f += THREADS;
        l += 1024u;
        j += 1u; s += 34u;
        if (j == Wc) { j = 0u; s -= 30u; }
        if (l >= nextB) { s += 30u; nextB += PER_B; }
    }
}

extern "C" void kernel_launch(void* const* d_in, const int* in_sizes, int n_in,
                              void* d_out, int out_size) {
    const float* x = (const float*)d_in[0];
    (void)in_sizes; (void)n_in; (void)out_size;

    unsigned blocks = (N4 + F4_PER_BLOCK - 1) / F4_PER_BLOCK;   // 5272
    unfold_smem_kernel<<<blocks, THREADS>>>(x, (float4*)d_out);
}